// round 1
// baseline (speedup 1.0000x reference)
#include <cuda_runtime.h>

#define BB 512
#define TT 1024
#define HH 100
#define VV 62
#define NL 3

// scratch: ping-pong [T][B][H] time-major activation buffers (no cudaMalloc allowed)
__device__ float g_bufA[(size_t)TT * BB * HH];
__device__ float g_bufB[(size_t)TT * BB * HH];

// ---------------------------------------------------------------------------
// 1) embedding gather: x[t][b][:] = emb[ids[b][t]][:]   (time-major output)
// ---------------------------------------------------------------------------
__global__ void k_gather(const int* __restrict__ ids,
                         const float* __restrict__ emb,
                         float* __restrict__ out) {
    int idx = blockIdx.x * blockDim.x + threadIdx.x;  // over T*B*25 float4s
    if (idx >= TT * BB * 25) return;
    int c  = idx % 25;
    int tb = idx / 25;
    int b  = tb % BB;
    int t  = tb / BB;
    int id = ids[(size_t)b * TT + t];
    float4 v = ((const float4*)(emb + (size_t)id * HH))[c];
    ((float4*)(out + ((size_t)t * BB + b) * HH))[c] = v;
}

// ---------------------------------------------------------------------------
// 2) input projection: Y[row][k] = sum_j X[row][j]*W[k][j] + bi[k] + bh[k]
//    rows = T*B (time-major). Tile: 64 rows/block, 256 threads.
//    Dynamic smem: Wt[100][100] (transposed) + Xs[64][104] + bias[104]
// ---------------------------------------------------------------------------
__global__ void __launch_bounds__(256) k_proj(const float* __restrict__ X,
                                              const float* __restrict__ W,
                                              const float* __restrict__ bi,
                                              const float* __restrict__ bh,
                                              float* __restrict__ Y) {
    extern __shared__ float sm[];
    float* Wt = sm;                 // [100][100]  Wt[j*100 + k]
    float* Xs = sm + HH * HH;       // [64][104]
    float* bs = Xs + 64 * 104;      // [104]

    int tid = threadIdx.x;
    for (int i = tid; i < HH * HH; i += 256) {
        int k = i / HH, j = i % HH;
        Wt[j * HH + k] = W[i];
    }
    if (tid < 104) bs[tid] = (tid < HH) ? (bi[tid] + bh[tid]) : 0.0f;

    size_t row0 = (size_t)blockIdx.x * 64;
    for (int i = tid; i < 64 * 25; i += 256) {
        int r = i / 25, c = i % 25;
        float4 v = ((const float4*)(X + (row0 + r) * HH))[c];
        ((float4*)(Xs + r * 104))[c] = v;
    }
    __syncthreads();

    int k  = tid & 127;
    int y  = tid >> 7;              // 0..1 -> 32 rows each
    int kk = (k < HH) ? k : (HH - 1);

    for (int chunk = 0; chunk < 4; ++chunk) {
        int rbase = y * 32 + chunk * 8;
        float acc[8];
#pragma unroll
        for (int r = 0; r < 8; r++) acc[r] = bs[kk];
#pragma unroll
        for (int j4 = 0; j4 < 25; j4++) {
            float w0 = Wt[(j4 * 4 + 0) * HH + kk];
            float w1 = Wt[(j4 * 4 + 1) * HH + kk];
            float w2 = Wt[(j4 * 4 + 2) * HH + kk];
            float w3 = Wt[(j4 * 4 + 3) * HH + kk];
#pragma unroll
            for (int r = 0; r < 8; r++) {
                float4 x = ((const float4*)(Xs + (rbase + r) * 104))[j4];
                acc[r] += x.x * w0 + x.y * w1 + x.z * w2 + x.w * w3;
            }
        }
        if (k < HH) {
#pragma unroll
            for (int r = 0; r < 8; r++)
                Y[(row0 + rbase + r) * HH + k] = acc[r];
        }
    }
}

// ---------------------------------------------------------------------------
// 3) recurrent scan (per layer), in-place on XY (time-major [T][B][H]):
//    h_new = tanh(xin[t] + h @ Wh^T), writes ys back into XY[t].
//    Block = 4 batch rows, 128 threads (k dim), whole T loop in-kernel.
//    Wh row-major in smem (stride 100, conflict-free for 8-lane LDS.128 phases);
//    xin for step t+1 prefetched during step-t FMAs.
// ---------------------------------------------------------------------------
__global__ void __launch_bounds__(128) k_rnn(float* __restrict__ XY,
                                             const float* __restrict__ W,
                                             float* __restrict__ hout) {
    __shared__ float Ws[HH * HH];   // [k][j], stride 100
    __shared__ float hs[4][104];

    int tid = threadIdx.x;          // 128
    for (int i = tid; i < HH * HH; i += 128) Ws[i] = W[i];
    if (tid < 104) {
        hs[0][tid] = 0.f; hs[1][tid] = 0.f; hs[2][tid] = 0.f; hs[3][tid] = 0.f;
    }
    __syncthreads();

    int k  = tid;
    int kk = (k < HH) ? k : (HH - 1);
    int b0 = blockIdx.x * 4;
    const float* wrow = &Ws[kk * HH];
    const size_t stride_t = (size_t)BB * HH;
    const float* px = XY + (size_t)b0 * HH + kk;

    float c0 = px[0], c1 = px[HH], c2 = px[2 * HH], c3 = px[3 * HH];

    for (int t = 0; t < TT; t++) {
        // prefetch next step's xin
        size_t tn = (size_t)((t + 1 < TT) ? t + 1 : t) * stride_t;
        float n0 = px[tn], n1 = px[tn + HH], n2 = px[tn + 2 * HH], n3 = px[tn + 3 * HH];

        float a0 = c0, a1 = c1, a2 = c2, a3 = c3;
#pragma unroll
        for (int j4 = 0; j4 < 25; j4++) {
            float4 w  = *(const float4*)(wrow + j4 * 4);
            float4 h0 = *(const float4*)(&hs[0][j4 * 4]);
            float4 h1 = *(const float4*)(&hs[1][j4 * 4]);
            float4 h2 = *(const float4*)(&hs[2][j4 * 4]);
            float4 h3 = *(const float4*)(&hs[3][j4 * 4]);
            a0 += w.x * h0.x + w.y * h0.y + w.z * h0.z + w.w * h0.w;
            a1 += w.x * h1.x + w.y * h1.y + w.z * h1.z + w.w * h1.w;
            a2 += w.x * h2.x + w.y * h2.y + w.z * h2.z + w.w * h2.w;
            a3 += w.x * h3.x + w.y * h3.y + w.z * h3.z + w.w * h3.w;
        }
        a0 = tanhf(a0); a1 = tanhf(a1); a2 = tanhf(a2); a3 = tanhf(a3);

        __syncthreads();   // all hs reads of step t done
        if (k < HH) {
            hs[0][k] = a0; hs[1][k] = a1; hs[2][k] = a2; hs[3][k] = a3;
            float* py = XY + (size_t)t * stride_t + (size_t)b0 * HH + k;
            py[0] = a0; py[HH] = a1; py[2 * HH] = a2; py[3 * HH] = a3;
        }
        __syncthreads();   // hs writes visible for step t+1

        c0 = n0; c1 = n1; c2 = n2; c3 = n3;
    }

    if (k < HH) {
        hout[(size_t)(b0 + 0) * HH + k] = hs[0][k];
        hout[(size_t)(b0 + 1) * HH + k] = hs[1][k];
        hout[(size_t)(b0 + 2) * HH + k] = hs[2][k];
        hout[(size_t)(b0 + 3) * HH + k] = hs[3][k];
    }
}

// ---------------------------------------------------------------------------
// 4) decoder: logits[b][t][v] = dot(ys[t][b][:], Wd[v][:]) + bd[v]
//    rows = t*B+b (time-major input), output batch-major. 32 rows/block.
// ---------------------------------------------------------------------------
__global__ void __launch_bounds__(256) k_dec(const float* __restrict__ Ys,
                                             const float* __restrict__ Wd,
                                             const float* __restrict__ bd,
                                             float* __restrict__ out) {
    __shared__ float Wt[HH][64];    // Wt[j][v]
    __shared__ float Xs[32][104];
    __shared__ float bs[64];

    int tid = threadIdx.x;          // 256
    for (int i = tid; i < VV * HH; i += 256) {
        int v = i / HH, j = i % HH;
        Wt[j][v] = Wd[i];
    }
    if (tid < HH) { Wt[tid][62] = 0.f; Wt[tid][63] = 0.f; }
    if (tid < 64) bs[tid] = (tid < VV) ? bd[tid] : 0.f;

    size_t row0 = (size_t)blockIdx.x * 32;
    for (int i = tid; i < 32 * 25; i += 256) {
        int r = i / 25, c = i % 25;
        ((float4*)(&Xs[r][0]))[c] = ((const float4*)(Ys + (row0 + r) * HH))[c];
    }
    __syncthreads();

    int v = tid & 63;
    int y = tid >> 6;               // 0..3 -> 8 rows each
    float acc[8];
#pragma unroll
    for (int r = 0; r < 8; r++) acc[r] = bs[v];
#pragma unroll
    for (int j4 = 0; j4 < 25; j4++) {
        float w0 = Wt[j4 * 4 + 0][v];
        float w1 = Wt[j4 * 4 + 1][v];
        float w2 = Wt[j4 * 4 + 2][v];
        float w3 = Wt[j4 * 4 + 3][v];
#pragma unroll
        for (int r = 0; r < 8; r++) {
            float4 x = ((const float4*)(&Xs[y * 8 + r][0]))[j4];
            acc[r] += x.x * w0 + x.y * w1 + x.z * w2 + x.w * w3;
        }
    }
    if (v < VV) {
#pragma unroll
        for (int r = 0; r < 8; r++) {
            size_t row = row0 + y * 8 + r;     // = t*BB + b
            size_t t = row >> 9;               // /512
            size_t b = row & 511;
            out[(b * TT + t) * VV + v] = acc[r];
        }
    }
}

// ---------------------------------------------------------------------------
extern "C" void kernel_launch(void* const* d_in, const int* in_sizes, int n_in,
                              void* d_out, int out_size) {
    const int*   ids   = (const int*)d_in[0];
    const float* emb   = (const float*)d_in[1];
    const float* W_ih  = (const float*)d_in[2];   // [3][100][100]
    const float* W_hh  = (const float*)d_in[3];   // [3][100][100]
    const float* b_ih  = (const float*)d_in[4];   // [3][100]
    const float* b_hh  = (const float*)d_in[5];   // [3][100]
    const float* W_dec = (const float*)d_in[6];   // [62][100]
    const float* b_dec = (const float*)d_in[7];   // [62]
    float* out = (float*)d_out;

    float *bufA, *bufB;
    cudaGetSymbolAddress((void**)&bufA, g_bufA);
    cudaGetSymbolAddress((void**)&bufB, g_bufB);

    const int proj_smem = (HH * HH + 64 * 104 + 104) * (int)sizeof(float);  // ~68 KB
    cudaFuncSetAttribute(k_proj, cudaFuncAttributeMaxDynamicSharedMemorySize, proj_smem);

    // 1) embed gather into bufA (time-major)
    {
        int total = TT * BB * 25;
        k_gather<<<(total + 255) / 256, 256>>>(ids, emb, bufA);
    }

    float* X = bufA;
    float* Y = bufB;
    float* hidden_base = out + (size_t)BB * TT * VV;

    for (int l = 0; l < NL; l++) {
        k_proj<<<(TT * BB) / 64, 256, proj_smem>>>(
            X, W_ih + (size_t)l * HH * HH, b_ih + l * HH, b_hh + l * HH, Y);
        k_rnn<<<BB / 4, 128>>>(Y, W_hh + (size_t)l * HH * HH,
                               hidden_base + (size_t)l * BB * HH);
        float* tmp = X; X = Y; Y = tmp;   // ys now lives in X
    }

    k_dec<<<(TT * BB) / 32, 256>>>(X, W_dec, b_dec, out);
}